// round 11
// baseline (speedup 1.0000x reference)
#include <cuda_runtime.h>
#include <cstdint>
#include <cstring>

#define Bx 64
#define Cx 3
#define Hx 384
#define Wx 384
#define PLANE (Hx * Wx)          // 147456
#define IMGS_PER_TEX 16
#define TEX_H (IMGS_PER_TEX * Cx * Hx)   // 18432 rows

// ---------------- texture-gather kernel (pair-pipelined) ----------------
__global__ __launch_bounds__(256, 5) void affine_tex_kernel(
    cudaTextureObject_t t0, cudaTextureObject_t t1,
    cudaTextureObject_t t2, cudaTextureObject_t t3,
    const float* __restrict__ theta,
    float* __restrict__ out)
{
    int lane  = threadIdx.x;          // 0..31
    int w     = threadIdx.y;          // 0..7
    int warpx = w & 3;
    int warpy = w >> 2;

    int x     = blockIdx.x * 128 + warpx * 32 + lane;
    int ybase = blockIdx.y * 8 + warpy * 4;
    int b     = blockIdx.z;

    const float* th = theta + b * 6;
    float t00 = __ldg(th + 0), t01 = __ldg(th + 1), t02 = __ldg(th + 2);
    float t10 = __ldg(th + 3), t11 = __ldg(th + 4), t12 = __ldg(th + 5);

    cudaTextureObject_t tex = (b & 32) ? ((b & 16) ? t3 : t2)
                                       : ((b & 16) ? t1 : t0);
    float rowb = (float)((b & (IMGS_PER_TEX - 1)) * Cx * Hx);  // channel-0 base row

    float xv  = (float)x - 191.5f;
    float ixx = fmaf(xv, t00, t02 + 191.5f);
    float iyx = fmaf(xv, t10, t12 + 191.5f);

    float* outb = out + (size_t)b * (Cx * PLANE);

    // Process the 4 rows as 2 pairs; each pair keeps 6 gathers in flight
    // before any consume, doubling TEX MLP vs the per-row version.
#pragma unroll
    for (int p = 0; p < 2; p++) {
        int ya = ybase + 2 * p;
        int yb = ya + 1;

        // ---- coords & weights for both rows ----
        float yva = (float)ya - 191.5f;
        float ixa = fmaf(yva, t01, ixx);
        float iya = fmaf(yva, t11, iyx);
        float yvb = (float)yb - 191.5f;
        float ixb = fmaf(yvb, t01, ixx);
        float iyb = fmaf(yvb, t11, iyx);

        float fxa = floorf(ixa), fya = floorf(iya);
        float fxb = floorf(ixb), fyb = floorf(iyb);

        float wxa1 = ixa - fxa, wya1 = iya - fya;
        float wxa0 = 1.0f - wxa1, wya0 = 1.0f - wya1;
        float wxb1 = ixb - fxb, wyb1 = iyb - fyb;
        float wxb0 = 1.0f - wxb1, wyb0 = 1.0f - wyb1;

        int y0a = (int)fya, y1a = y0a + 1;
        int y0b = (int)fyb, y1b = y0b + 1;

        float vya0 = (y0a >= 0 && y0a < Hx) ? wya0 : 0.0f;
        float vya1 = (y1a >= 0 && y1a < Hx) ? wya1 : 0.0f;
        float vyb0 = (y0b >= 0 && y0b < Hx) ? wyb0 : 0.0f;
        float vyb1 = (y1b >= 0 && y1b < Hx) ? wyb1 : 0.0f;

        float a00 = wxa0 * vya0, a10 = wxa1 * vya0;
        float a01 = wxa0 * vya1, a11 = wxa1 * vya1;
        float b00 = wxb0 * vyb0, b10 = wxb1 * vyb0;
        float b01 = wxb0 * vyb1, b11 = wxb1 * vyb1;

        float gxa = fxa + 1.0f, gya = rowb + fya + 1.0f;
        float gxb = fxb + 1.0f, gyb = rowb + fyb + 1.0f;

        // ---- issue all 6 gathers (2 rows x 3 channels) ----
        float4 gA0 = tex2Dgather<float4>(tex, gxa, gya, 0);
        float4 gB0 = tex2Dgather<float4>(tex, gxb, gyb, 0);
        float4 gA1 = tex2Dgather<float4>(tex, gxa, gya + (float)Hx, 0);
        float4 gB1 = tex2Dgather<float4>(tex, gxb, gyb + (float)Hx, 0);
        float4 gA2 = tex2Dgather<float4>(tex, gxa, gya + (float)(2 * Hx), 0);
        float4 gB2 = tex2Dgather<float4>(tex, gxb, gyb + (float)(2 * Hx), 0);

        // gather order: .w=(x0,y0) .z=(x1,y0) .x=(x0,y1) .y=(x1,y1)
        float ra0 = fmaf(a00, gA0.w, fmaf(a10, gA0.z, fmaf(a01, gA0.x, a11 * gA0.y)));
        float ra1 = fmaf(a00, gA1.w, fmaf(a10, gA1.z, fmaf(a01, gA1.x, a11 * gA1.y)));
        float ra2 = fmaf(a00, gA2.w, fmaf(a10, gA2.z, fmaf(a01, gA2.x, a11 * gA2.y)));
        float rb0 = fmaf(b00, gB0.w, fmaf(b10, gB0.z, fmaf(b01, gB0.x, b11 * gB0.y)));
        float rb1 = fmaf(b00, gB1.w, fmaf(b10, gB1.z, fmaf(b01, gB1.x, b11 * gB1.y)));
        float rb2 = fmaf(b00, gB2.w, fmaf(b10, gB2.z, fmaf(b01, gB2.x, b11 * gB2.y)));

        int offa = ya * Wx + x;
        int offb = yb * Wx + x;
        outb[0 * PLANE + offa] = ra0;
        outb[1 * PLANE + offa] = ra1;
        outb[2 * PLANE + offa] = ra2;
        outb[0 * PLANE + offb] = rb0;
        outb[1 * PLANE + offb] = rb1;
        outb[2 * PLANE + offb] = rb2;
    }
}

// ---------------- fallback: proven R3 global-gather kernel ----------------
__global__ __launch_bounds__(256) void affine_ldg_kernel(
    const float* __restrict__ imgs,
    const float* __restrict__ theta,
    float* __restrict__ out)
{
    int lane  = threadIdx.x;
    int w     = threadIdx.y;
    int warpx = w & 3;
    int warpy = w >> 2;

    int x     = blockIdx.x * 128 + warpx * 32 + lane;
    int ybase = blockIdx.y * 8 + warpy * 4;
    int b     = blockIdx.z;

    const float* th = theta + b * 6;
    float t00 = __ldg(th + 0), t01 = __ldg(th + 1), t02 = __ldg(th + 2);
    float t10 = __ldg(th + 3), t11 = __ldg(th + 4), t12 = __ldg(th + 5);

    float xv  = (float)x - 191.5f;
    float ixx = fmaf(xv, t00, t02 + 191.5f);
    float iyx = fmaf(xv, t10, t12 + 191.5f);

    const float* img  = imgs + (size_t)b * (Cx * PLANE);
    float*       outb = out  + (size_t)b * (Cx * PLANE);

#pragma unroll
    for (int r = 0; r < 4; r++) {
        int y = ybase + r;
        float yv = (float)y - 191.5f;
        float ix = fmaf(yv, t01, ixx);
        float iy = fmaf(yv, t11, iyx);

        float fx0 = floorf(ix), fy0 = floorf(iy);
        float wx1 = ix - fx0,  wy1 = iy - fy0;
        float wx0 = 1.0f - wx1, wy0 = 1.0f - wy1;

        int x0 = (int)fx0, y0 = (int)fy0;
        int x1 = x0 + 1,  y1 = y0 + 1;

        float vx0 = (x0 >= 0 && x0 < Wx) ? 1.0f : 0.0f;
        float vx1 = (x1 >= 0 && x1 < Wx) ? 1.0f : 0.0f;
        float vy0 = (y0 >= 0 && y0 < Hx) ? 1.0f : 0.0f;
        float vy1 = (y1 >= 0 && y1 < Hx) ? 1.0f : 0.0f;

        float w00 = wx0 * wy0 * vx0 * vy0;
        float w10 = wx1 * wy0 * vx1 * vy0;
        float w01 = wx0 * wy1 * vx0 * vy1;
        float w11 = wx1 * wy1 * vx1 * vy1;

        int xc0 = min(max(x0, 0), Wx - 1);
        int xc1 = min(max(x1, 0), Wx - 1);
        int yc0 = min(max(y0, 0), Hx - 1);
        int yc1 = min(max(y1, 0), Hx - 1);

        int o00 = yc0 * Wx + xc0;
        int o10 = yc0 * Wx + xc1;
        int o01 = yc1 * Wx + xc0;
        int o11 = yc1 * Wx + xc1;

        float v00c0 = __ldg(img + 0 * PLANE + o00);
        float v10c0 = __ldg(img + 0 * PLANE + o10);
        float v01c0 = __ldg(img + 0 * PLANE + o01);
        float v11c0 = __ldg(img + 0 * PLANE + o11);
        float v00c1 = __ldg(img + 1 * PLANE + o00);
        float v10c1 = __ldg(img + 1 * PLANE + o10);
        float v01c1 = __ldg(img + 1 * PLANE + o01);
        float v11c1 = __ldg(img + 1 * PLANE + o11);
        float v00c2 = __ldg(img + 2 * PLANE + o00);
        float v10c2 = __ldg(img + 2 * PLANE + o10);
        float v01c2 = __ldg(img + 2 * PLANE + o01);
        float v11c2 = __ldg(img + 2 * PLANE + o11);

        float r0 = fmaf(w00, v00c0, fmaf(w10, v10c0, fmaf(w01, v01c0, w11 * v11c0)));
        float r1 = fmaf(w00, v00c1, fmaf(w10, v10c1, fmaf(w01, v01c1, w11 * v11c1)));
        float r2 = fmaf(w00, v00c2, fmaf(w10, v10c2, fmaf(w01, v01c2, w11 * v11c2)));

        int rowoff = y * Wx + x;
        outb[0 * PLANE + rowoff] = r0;
        outb[1 * PLANE + rowoff] = r1;
        outb[2 * PLANE + rowoff] = r2;
    }
}

extern "C" void kernel_launch(void* const* d_in, const int* in_sizes, int n_in,
                              void* d_out, int out_size)
{
    const float* imgs  = (const float*)d_in[0];
    const float* theta = (const float*)d_in[1];
    float* out = (float*)d_out;

    // One-time texture-object setup OUTSIDE any graph capture (proven pattern):
    // the correctness call builds the views; captured call + replays contain
    // only the kernel launch. Deterministic work on every call.
    static cudaTextureObject_t tex[4] = {0, 0, 0, 0};
    static const float* cached_imgs = nullptr;
    static int tex_ok = 0;

    if (cached_imgs != imgs) {
        cudaStreamCaptureStatus cs = cudaStreamCaptureStatusNone;
        cudaStreamIsCapturing(cudaStreamLegacy, &cs);
        if (cs == cudaStreamCaptureStatusNone) {
            int ok = 1;
            for (int g = 0; g < 4 && ok; g++) {
                cudaResourceDesc rd;
                memset(&rd, 0, sizeof(rd));
                rd.resType = cudaResourceTypePitch2D;
                rd.res.pitch2D.devPtr =
                    (void*)(imgs + (size_t)g * IMGS_PER_TEX * Cx * PLANE);
                rd.res.pitch2D.desc = cudaCreateChannelDesc<float>();
                rd.res.pitch2D.width = Wx;
                rd.res.pitch2D.height = TEX_H;
                rd.res.pitch2D.pitchInBytes = Wx * sizeof(float);

                cudaTextureDesc td;
                memset(&td, 0, sizeof(td));
                td.addressMode[0] = cudaAddressModeBorder;  // OOB -> 0
                td.addressMode[1] = cudaAddressModeBorder;
                td.filterMode = cudaFilterModePoint;
                td.readMode = cudaReadModeElementType;
                td.normalizedCoords = 0;

                if (cudaCreateTextureObject(&tex[g], &rd, &td, nullptr)
                    != cudaSuccess) ok = 0;
            }
            tex_ok = ok;
            cached_imgs = imgs;
        }
    }

    dim3 block(32, 8);
    dim3 grid(Wx / 128, Hx / 8, Bx);   // (3, 48, 64)
    if (tex_ok && cached_imgs == imgs) {
        affine_tex_kernel<<<grid, block>>>(tex[0], tex[1], tex[2], tex[3],
                                           theta, out);
    } else {
        affine_ldg_kernel<<<grid, block>>>(imgs, theta, out);
    }
}

// round 12
// speedup vs baseline: 1.1565x; 1.1565x over previous
#include <cuda_runtime.h>
#include <cstdint>
#include <cstring>

#define Bx 64
#define Cx 3
#define Hx 384
#define Wx 384
#define PLANE (Hx * Wx)          // 147456
#define IMGS_PER_TEX 16
#define TEX_H (IMGS_PER_TEX * Cx * Hx)   // 18432 rows

// ---------------- hybrid kernel: TEX pipe for even images, LSU pipe for odd ----------------
__global__ __launch_bounds__(256) void affine_hybrid_kernel(
    cudaTextureObject_t t0, cudaTextureObject_t t1,
    cudaTextureObject_t t2, cudaTextureObject_t t3,
    const float* __restrict__ imgs,
    const float* __restrict__ theta,
    float* __restrict__ out,
    int tex_ok)
{
    int lane  = threadIdx.x;          // 0..31
    int w     = threadIdx.y;          // 0..7
    int warpx = w & 3;
    int warpy = w >> 2;

    int x     = blockIdx.x * 128 + warpx * 32 + lane;
    int ybase = blockIdx.y * 8 + warpy * 4;
    int b     = blockIdx.z;

    const float* th = theta + b * 6;
    float t00 = __ldg(th + 0), t01 = __ldg(th + 1), t02 = __ldg(th + 2);
    float t10 = __ldg(th + 3), t11 = __ldg(th + 4), t12 = __ldg(th + 5);

    float xv  = (float)x - 191.5f;
    float ixx = fmaf(xv, t00, t02 + 191.5f);
    float iyx = fmaf(xv, t10, t12 + 191.5f);

    float* outb = out + (size_t)b * (Cx * PLANE);

    if (tex_ok && (b & 1) == 0) {
        // ================= TEX path (texture filter pipe) =================
        cudaTextureObject_t tex = (b & 32) ? ((b & 16) ? t3 : t2)
                                           : ((b & 16) ? t1 : t0);
        float rowb = (float)((b & (IMGS_PER_TEX - 1)) * Cx * Hx);

#pragma unroll
        for (int r = 0; r < 4; r++) {
            int y = ybase + r;
            float yv = (float)y - 191.5f;
            float ix = fmaf(yv, t01, ixx);
            float iy = fmaf(yv, t11, iyx);

            float fx0 = floorf(ix);
            float fy0 = floorf(iy);
            float wx1 = ix - fx0;
            float wy1 = iy - fy0;
            float wx0 = 1.0f - wx1;
            float wy0 = 1.0f - wy1;

            int y0 = (int)fy0;
            int y1 = y0 + 1;
            float vy0 = (y0 >= 0 && y0 < Hx) ? wy0 : 0.0f;
            float vy1 = (y1 >= 0 && y1 < Hx) ? wy1 : 0.0f;

            float w00 = wx0 * vy0, w10 = wx1 * vy0;
            float w01 = wx0 * vy1, w11 = wx1 * vy1;

            float gx = fx0 + 1.0f;
            float gy = rowb + fy0 + 1.0f;

            float4 g0 = tex2Dgather<float4>(tex, gx, gy, 0);
            float4 g1 = tex2Dgather<float4>(tex, gx, gy + (float)Hx, 0);
            float4 g2 = tex2Dgather<float4>(tex, gx, gy + (float)(2 * Hx), 0);

            // gather order: .w=(x0,y0) .z=(x1,y0) .x=(x0,y1) .y=(x1,y1)
            float r0 = fmaf(w00, g0.w, fmaf(w10, g0.z, fmaf(w01, g0.x, w11 * g0.y)));
            float r1 = fmaf(w00, g1.w, fmaf(w10, g1.z, fmaf(w01, g1.x, w11 * g1.y)));
            float r2 = fmaf(w00, g2.w, fmaf(w10, g2.z, fmaf(w01, g2.x, w11 * g2.y)));

            int rowoff = y * Wx + x;
            outb[0 * PLANE + rowoff] = r0;
            outb[1 * PLANE + rowoff] = r1;
            outb[2 * PLANE + rowoff] = r2;
        }
    } else {
        // ================= LDG path (LSU pipe) =================
        const float* img = imgs + (size_t)b * (Cx * PLANE);

#pragma unroll
        for (int r = 0; r < 4; r++) {
            int y = ybase + r;
            float yv = (float)y - 191.5f;
            float ix = fmaf(yv, t01, ixx);
            float iy = fmaf(yv, t11, iyx);

            float fx0 = floorf(ix), fy0 = floorf(iy);
            float wx1 = ix - fx0,  wy1 = iy - fy0;
            float wx0 = 1.0f - wx1, wy0 = 1.0f - wy1;

            int x0 = (int)fx0, y0 = (int)fy0;
            int x1 = x0 + 1,  y1 = y0 + 1;

            float vx0 = (x0 >= 0 && x0 < Wx) ? 1.0f : 0.0f;
            float vx1 = (x1 >= 0 && x1 < Wx) ? 1.0f : 0.0f;
            float vy0 = (y0 >= 0 && y0 < Hx) ? 1.0f : 0.0f;
            float vy1 = (y1 >= 0 && y1 < Hx) ? 1.0f : 0.0f;

            float w00 = wx0 * wy0 * vx0 * vy0;
            float w10 = wx1 * wy0 * vx1 * vy0;
            float w01 = wx0 * wy1 * vx0 * vy1;
            float w11 = wx1 * wy1 * vx1 * vy1;

            int xc0 = min(max(x0, 0), Wx - 1);
            int xc1 = min(max(x1, 0), Wx - 1);
            int yc0 = min(max(y0, 0), Hx - 1);
            int yc1 = min(max(y1, 0), Hx - 1);

            int o00 = yc0 * Wx + xc0;
            int o10 = yc0 * Wx + xc1;
            int o01 = yc1 * Wx + xc0;
            int o11 = yc1 * Wx + xc1;

            float v00c0 = __ldg(img + 0 * PLANE + o00);
            float v10c0 = __ldg(img + 0 * PLANE + o10);
            float v01c0 = __ldg(img + 0 * PLANE + o01);
            float v11c0 = __ldg(img + 0 * PLANE + o11);
            float v00c1 = __ldg(img + 1 * PLANE + o00);
            float v10c1 = __ldg(img + 1 * PLANE + o10);
            float v01c1 = __ldg(img + 1 * PLANE + o01);
            float v11c1 = __ldg(img + 1 * PLANE + o11);
            float v00c2 = __ldg(img + 2 * PLANE + o00);
            float v10c2 = __ldg(img + 2 * PLANE + o10);
            float v01c2 = __ldg(img + 2 * PLANE + o01);
            float v11c2 = __ldg(img + 2 * PLANE + o11);

            float r0 = fmaf(w00, v00c0, fmaf(w10, v10c0, fmaf(w01, v01c0, w11 * v11c0)));
            float r1 = fmaf(w00, v00c1, fmaf(w10, v10c1, fmaf(w01, v01c1, w11 * v11c1)));
            float r2 = fmaf(w00, v00c2, fmaf(w10, v10c2, fmaf(w01, v01c2, w11 * v11c2)));

            int rowoff = y * Wx + x;
            outb[0 * PLANE + rowoff] = r0;
            outb[1 * PLANE + rowoff] = r1;
            outb[2 * PLANE + rowoff] = r2;
        }
    }
}

extern "C" void kernel_launch(void* const* d_in, const int* in_sizes, int n_in,
                              void* d_out, int out_size)
{
    const float* imgs  = (const float*)d_in[0];
    const float* theta = (const float*)d_in[1];
    float* out = (float*)d_out;

    // One-time texture-object setup OUTSIDE graph capture (proven pattern).
    static cudaTextureObject_t tex[4] = {0, 0, 0, 0};
    static const float* cached_imgs = nullptr;
    static int tex_ok = 0;

    if (cached_imgs != imgs) {
        cudaStreamCaptureStatus cs = cudaStreamCaptureStatusNone;
        cudaStreamIsCapturing(cudaStreamLegacy, &cs);
        if (cs == cudaStreamCaptureStatusNone) {
            int ok = 1;
            for (int g = 0; g < 4 && ok; g++) {
                cudaResourceDesc rd;
                memset(&rd, 0, sizeof(rd));
                rd.resType = cudaResourceTypePitch2D;
                rd.res.pitch2D.devPtr =
                    (void*)(imgs + (size_t)g * IMGS_PER_TEX * Cx * PLANE);
                rd.res.pitch2D.desc = cudaCreateChannelDesc<float>();
                rd.res.pitch2D.width = Wx;
                rd.res.pitch2D.height = TEX_H;
                rd.res.pitch2D.pitchInBytes = Wx * sizeof(float);

                cudaTextureDesc td;
                memset(&td, 0, sizeof(td));
                td.addressMode[0] = cudaAddressModeBorder;  // OOB -> 0
                td.addressMode[1] = cudaAddressModeBorder;
                td.filterMode = cudaFilterModePoint;
                td.readMode = cudaReadModeElementType;
                td.normalizedCoords = 0;

                if (cudaCreateTextureObject(&tex[g], &rd, &td, nullptr)
                    != cudaSuccess) ok = 0;
            }
            tex_ok = ok;
            cached_imgs = imgs;
        }
    }

    int use_tex = (tex_ok && cached_imgs == imgs) ? 1 : 0;

    dim3 block(32, 8);
    dim3 grid(Wx / 128, Hx / 8, Bx);   // (3, 48, 64)
    affine_hybrid_kernel<<<grid, block>>>(tex[0], tex[1], tex[2], tex[3],
                                          imgs, theta, out, use_tex);
}